// round 1
// baseline (speedup 1.0000x reference)
#include <cuda_runtime.h>

// Problem constants (fixed by the reference).
#define B_DIM   16384
#define T_DIM   512
#define M_DIM   128
#define HOR     32
#define NSTEP   (T_DIM + B_DIM - 1)   // 16895 scan steps
#define NPAD    16896                 // 132 * 128, padded for unguarded float4 I/O
#define NBLK    132                   // blocks of 128 steps (= queue depth M)

// Scratch (allocation-free rule: __device__ globals).
__device__ float g_ts[NPAD];
__device__ float g_xnorm[NPAD];
__device__ float g_levels[NPAD];
__device__ float g_sseq[NPAD];

__device__ __forceinline__ float frcp(float x) {
    float r;
    asm("rcp.approx.ftz.f32 %0, %1;" : "=f"(r) : "f"(x));
    return r;
}

// ---------------------------------------------------------------------------
// Kernel 1: gather the effective time series ts[16895] from x.
// ts[i] = x[0,i,0] for i<512 ; x[i-511, 511, 0] otherwise. Pad slot -> 1.0f.
// ---------------------------------------------------------------------------
__global__ void prep_kernel(const float* __restrict__ x) {
    int i = blockIdx.x * blockDim.x + threadIdx.x;
    if (i < NPAD) {
        float v;
        if (i < T_DIM)       v = x[i];
        else if (i < NSTEP)  v = x[(i - (T_DIM - 1)) * T_DIM + (T_DIM - 1)];
        else                 v = 1.0f;  // pad
        g_ts[i] = v;
    }
}

// ---------------------------------------------------------------------------
// Kernel 2: single-warp blocked scan.
// Block = 128 steps (queue depth). s_t used at step t equals s_new from t-128,
// i.e. the value this same lane/slot produced last block -> queue lives in
// registers (4 per lane, consecutive steps). Level recurrence
//   l_t = c_t + k*l_{t-1},  c_t = a*y_t/s_t,  k = 1-alpha
// is a constant-coefficient linear scan -> Kogge-Stone over 32 lane-aggregates
// with stage coefficients k^(4*2^d).
// ---------------------------------------------------------------------------
__global__ void __launch_bounds__(32, 1)
scan_kernel(const float* __restrict__ alpha, const float* __restrict__ gamma,
            const float* __restrict__ init_s, const float* __restrict__ level0) {
    const unsigned FULL = 0xFFFFFFFFu;
    const int lane = threadIdx.x;

    const float a   = alpha[0];
    const float g   = gamma[0];
    const float k   = 1.0f - a;
    const float omg = 1.0f - g;
    const float k2  = k * k;
    const float k4  = k2 * k2;
    // Scan stage coefficients: k4^(2^d)
    const float K0 = k4, K1 = K0 * K0, K2c = K1 * K1, K3 = K2c * K2c, K4 = K3 * K3;
    // Carry-in coefficient for this lane: k^(4*(lane+1))
    float kp4 = k4;
    for (int i = 0; i < lane; ++i) kp4 *= k4;

    float l_in = level0[0];

    const int t0 = lane * 4;
    // Initial seasonality queue: steps 0..127 use init_s[0..127].
    float4 sv = *reinterpret_cast<const float4*>(init_s + t0);
    float s0 = sv.x, s1 = sv.y, s2 = sv.z, s3 = sv.w;
    float rs0 = frcp(s0), rs1 = frcp(s1), rs2 = frcp(s2), rs3 = frcp(s3);

    float4 yv = *reinterpret_cast<const float4*>(g_ts + t0);  // block 0 prefetch

    for (int blk = 0; blk < NBLK; ++blk) {
        const int base = blk * 128 + t0;

        // Prefetch next block's y while this block's chain runs.
        float4 ynext = make_float4(1.f, 1.f, 1.f, 1.f);
        if (blk + 1 < NBLK)
            ynext = *reinterpret_cast<const float4*>(g_ts + base + 128);

        const float y0 = yv.x, y1 = yv.y, y2 = yv.z, y3 = yv.w;

        // c_t = a*y_t / s_t  (all divisors known at block entry)
        const float c0 = (a * y0) * rs0;
        const float c1 = (a * y1) * rs1;
        const float c2 = (a * y2) * rs2;
        const float c3 = (a * y3) * rs3;

        // Lane aggregate over its 4 steps: B = c3 + k*c2 + k^2*c1 + k^3*c0 (depth-2 tree)
        const float u = fmaf(k, c2, c3);
        const float v = fmaf(k, c0, c1);
        float C = fmaf(k2, v, u);

        // Warp inclusive scan with geometric coefficients.
        float tC;
        tC = __shfl_up_sync(FULL, C, 1);  if (lane >= 1)  C = fmaf(K0,  tC, C);
        tC = __shfl_up_sync(FULL, C, 2);  if (lane >= 2)  C = fmaf(K1,  tC, C);
        tC = __shfl_up_sync(FULL, C, 4);  if (lane >= 4)  C = fmaf(K2c, tC, C);
        tC = __shfl_up_sync(FULL, C, 8);  if (lane >= 8)  C = fmaf(K3,  tC, C);
        tC = __shfl_up_sync(FULL, C, 16); if (lane >= 16) C = fmaf(K4,  tC, C);

        // Level at this lane's last step, then recover the 4 per-step levels.
        const float l_end = fmaf(kp4, l_in, C);
        float lp = __shfl_up_sync(FULL, l_end, 1);
        if (lane == 0) lp = l_in;
        const float l0 = fmaf(k, lp, c0);
        const float l1 = fmaf(k, l0, c1);
        const float l2 = fmaf(k, l1, c2);
        const float l3 = fmaf(k, l2, c3);

        const float rl0 = frcp(l0), rl1 = frcp(l1), rl2 = frcp(l2), rl3 = frcp(l3);

        // s_new = g*y/l + (1-g)*s ;  x_norm = y/(s*l) = y*rcp_s*rcp_l
        const float sn0 = fmaf(omg, s0, (g * y0) * rl0);
        const float sn1 = fmaf(omg, s1, (g * y1) * rl1);
        const float sn2 = fmaf(omg, s2, (g * y2) * rl2);
        const float sn3 = fmaf(omg, s3, (g * y3) * rl3);

        const float xn0 = (y0 * rs0) * rl0;
        const float xn1 = (y1 * rs1) * rl1;
        const float xn2 = (y2 * rs2) * rl2;
        const float xn3 = (y3 * rs3) * rl3;

        // Stores are off the critical path; pad slot absorbs the tail garbage.
        *reinterpret_cast<float4*>(g_xnorm  + base) = make_float4(xn0, xn1, xn2, xn3);
        *reinterpret_cast<float4*>(g_levels + base) = make_float4(l0, l1, l2, l3);
        *reinterpret_cast<float4*>(g_sseq   + base) = make_float4(sn0, sn1, sn2, sn3);

        // Next-block state: queue rotates through registers.
        s0 = sn0; s1 = sn1; s2 = sn2; s3 = sn3;
        rs0 = frcp(sn0); rs1 = frcp(sn1); rs2 = frcp(sn2); rs3 = frcp(sn3);
        l_in = __shfl_sync(FULL, l3, 31);
        yv = ynext;
    }
}

// ---------------------------------------------------------------------------
// Kernel 3: materialize outputs (pure bandwidth).
//   x_out[b,t]        = x_norm[b+t]                     (float4 stores)
//   denorm[b,h,{0,1}] = (levels[b+511], s_seq[b+384+h]) (float2 stores)
// ---------------------------------------------------------------------------
__global__ void __launch_bounds__(256)
out_kernel(float* __restrict__ out) {
    const int XQUADS = (B_DIM * T_DIM) / 4;  // 2097152
    int tid = blockIdx.x * blockDim.x + threadIdx.x;
    if (tid < XQUADS) {
        int idx = tid * 4;
        int b = idx >> 9;        // / 512
        int t = idx & 511;
        int s = b + t;
        float4 v = make_float4(g_xnorm[s], g_xnorm[s + 1], g_xnorm[s + 2], g_xnorm[s + 3]);
        *reinterpret_cast<float4*>(out + idx) = v;
    } else {
        int j = tid - XQUADS;    // 0 .. B*32-1
        if (j < B_DIM * HOR) {
            int b = j >> 5;
            int h = j & 31;
            float2 v = make_float2(g_levels[b + (T_DIM - 1)], g_sseq[b + 384 + h]);
            *reinterpret_cast<float2*>(out + B_DIM * T_DIM + 2 * j) = v;
        }
    }
}

// ---------------------------------------------------------------------------
// Launch. Inputs (metadata order): x, alpha, gamma, init_seasonality, level.
// ---------------------------------------------------------------------------
extern "C" void kernel_launch(void* const* d_in, const int* in_sizes, int n_in,
                              void* d_out, int out_size) {
    const float* x      = (const float*)d_in[0];
    const float* alpha  = (const float*)d_in[1];
    const float* gamma  = (const float*)d_in[2];
    const float* init_s = (const float*)d_in[3];
    const float* level  = (const float*)d_in[4];
    float* out = (float*)d_out;

    prep_kernel<<<(NPAD + 255) / 256, 256>>>(x);
    scan_kernel<<<1, 32>>>(alpha, gamma, init_s, level);
    const int total = (B_DIM * T_DIM) / 4 + B_DIM * HOR;  // 2621440
    out_kernel<<<total / 256, 256>>>(out);
}